// round 10
// baseline (speedup 1.0000x reference)
#include <cuda_runtime.h>
#include <math.h>

// Problem dims
#define TB   262144   // T*B = 256*1024
#define TT   256
#define BB   1024
#define NOUT 19
#define SM_TILES 25   // A-fragment m-tiles resident in smem (of 32)

// ---------------- scratch (static device memory; no allocs) ----------------
__device__ float g_h1[TB * 128];
__device__ float g_h2[TB * 32];
__device__ float g_h3[TB * 128];
__device__ float g_xg[TB * 512];
__device__ float g_hs[TB * 128];
__device__ float g_WhhFrag[32 * 16 * 32 * 4];  // [mtile][kstep][lane][reg], tf32
__device__ float g_bg[512];
__device__ float g_Whead[NOUT * 128];
__device__ float g_bhead[NOUT];

// ---------------- packed f32x2 helpers ----------------
typedef unsigned long long ull;
__device__ __forceinline__ ull pack2(float lo, float hi) {
    ull r; asm("mov.b64 %0, {%1, %2};" : "=l"(r) : "f"(lo), "f"(hi)); return r;
}
__device__ __forceinline__ void unpack2(ull p, float& lo, float& hi) {
    asm("mov.b64 {%0, %1}, %2;" : "=f"(lo), "=f"(hi) : "l"(p));
}
__device__ __forceinline__ ull ffma2(ull a, ull b, ull c) {
    ull d; asm("fma.rn.f32x2 %0, %1, %2, %3;" : "=l"(d) : "l"(a), "l"(b), "l"(c));
    return d;
}

// ---------------- tf32 helpers ----------------
__device__ __forceinline__ unsigned tf32_of(float f) {
    unsigned r; asm("cvt.rna.tf32.f32 %0, %1;" : "=r"(r) : "f"(f)); return r;
}
__device__ __forceinline__ void mma_tf32(float* d, const unsigned* a, const unsigned* b) {
    asm volatile(
        "mma.sync.aligned.m16n8k8.row.col.f32.tf32.tf32.f32 "
        "{%0,%1,%2,%3}, {%4,%5,%6,%7}, {%8,%9}, {%0,%1,%2,%3};"
        : "+f"(d[0]), "+f"(d[1]), "+f"(d[2]), "+f"(d[3])
        : "r"(a[0]), "r"(a[1]), "r"(a[2]), "r"(a[3]), "r"(b[0]), "r"(b[1]));
}

// ---------------- fast activations ----------------
__device__ __forceinline__ float sigmoid_f(float x) {
    return __fdividef(1.f, 1.f + __expf(-x));
}
__device__ __forceinline__ float tanh_f(float x) {
    float e = __expf(-2.f * fabsf(x));
    float r = __fdividef(1.f - e, 1.f + e);
    return copysignf(r, x);
}

// ---------------- prepack ----------------
// g_WhhFrag[mt][ks][lane][r]: exact mma.m16n8k8 A-fragment order (row-major A):
//   g = lane>>2, t = lane&3
//   r0=(g,t)  r1=(g+8,t)  r2=(g,t+4)  r3=(g+8,t+4)   rows = gates, cols = k
__global__ void prepack_kernel(const float* __restrict__ Whh,
                               const float* __restrict__ bih,
                               const float* __restrict__ bhh,
                               const float* __restrict__ Wa,
                               const float* __restrict__ ba,
                               const float* __restrict__ Wc,
                               const float* __restrict__ bc) {
    int t = blockIdx.x * blockDim.x + threadIdx.x;
    int stride = gridDim.x * blockDim.x;
    for (int i = t; i < 32 * 16 * 32 * 4; i += stride) {
        int r    = i & 3;
        int lane = (i >> 2) & 31;
        int ks   = (i >> 7) & 15;
        int mt   = i >> 11;
        int gg = lane >> 2, tg = lane & 3;
        int row = mt * 16 + gg + ((r & 1) ? 8 : 0);
        int col = ks * 8 + tg + ((r & 2) ? 4 : 0);
        g_WhhFrag[i] = __uint_as_float(tf32_of(Whh[row * 128 + col]));
    }
    if (t < 512) g_bg[t] = bih[t] + bhh[t];
    for (int i = t; i < NOUT * 128; i += stride) {
        int n = i / 128, k = i % 128;
        g_Whead[i] = (n < 18) ? Wa[n * 128 + k] : Wc[k];
    }
    if (t < NOUT) g_bhead[t] = (t < 18) ? ba[t] : bc[0];
}

// ================= TF32 tensor-core GEMM (feedforward) =================
template<int BN, int WARPS_M, int WARPS_N, bool RELU>
__global__ void __launch_bounds__(32 * WARPS_M * WARPS_N, 2)
tf32_gemm(const float* __restrict__ A, const float* __restrict__ W,
          const float* __restrict__ bias, float* __restrict__ C, int K) {
    constexpr int BM = 128;
    constexpr int BK = 32;
    constexpr int THREADS = 32 * WARPS_M * WARPS_N;
    constexpr int MT = (BM / WARPS_M) / 16;
    constexpr int NT = (BN / WARPS_N) / 8;

    __shared__ unsigned As[BM / 16][BK / 8][32][4];
    __shared__ unsigned Bs[BN / 8][BK / 16][32][4];

    const int tid  = threadIdx.x;
    const int lane = tid & 31;
    const int w    = tid >> 5;
    const int wm   = w / WARPS_N;
    const int wn   = w % WARPS_N;
    const int bm   = blockIdx.x * BM;
    const int bn   = blockIdx.y * BN;
    const int g    = lane >> 2;
    const int tig  = lane & 3;

    float acc[MT][NT][4];
#pragma unroll
    for (int i = 0; i < MT; i++)
#pragma unroll
        for (int j = 0; j < NT; j++)
#pragma unroll
            for (int r = 0; r < 4; r++) acc[i][j][r] = 0.f;

    for (int k0 = 0; k0 < K; k0 += BK) {
        constexpr int AV4 = BM * BK / 4;
#pragma unroll
        for (int it = 0; it < AV4 / THREADS; it++) {
            int idx = tid + it * THREADS;
            int row = idx >> 3;
            int c4  = idx & 7;
            float4 v = *(const float4*)(A + (size_t)(bm + row) * K + k0 + c4 * 4);
            int mt = row >> 4, r = row & 15;
            float vv[4] = {v.x, v.y, v.z, v.w};
#pragma unroll
            for (int j = 0; j < 4; j++) {
                int col = c4 * 4 + j;
                int kt = col >> 3, c = col & 7;
                As[mt][kt][(r & 7) * 4 + (c & 3)][(r >> 3) + 2 * (c >> 2)] = tf32_of(vv[j]);
            }
        }
        constexpr int BV4 = BN * BK / 4;
#pragma unroll
        for (int it = 0; it < (BV4 + THREADS - 1) / THREADS; it++) {
            int idx = tid + it * THREADS;
            if ((BV4 % THREADS == 0) || idx < BV4) {
                int n  = idx >> 3;
                int c4 = idx & 7;
                float4 v = *(const float4*)(W + (size_t)(bn + n) * K + k0 + c4 * 4);
                int nt = n >> 3, gg = n & 7;
                float vv[4] = {v.x, v.y, v.z, v.w};
#pragma unroll
                for (int j = 0; j < 4; j++) {
                    int k = c4 * 4 + j;
                    int kblk = k >> 4, kk = k & 15;
                    Bs[nt][kblk][gg * 4 + (kk & 3)][((kk >> 3) << 1) + ((kk & 7) >> 2)] = tf32_of(vv[j]);
                }
            }
        }
        __syncthreads();

#pragma unroll
        for (int kt = 0; kt < 4; kt++) {
            unsigned a[MT][4];
#pragma unroll
            for (int mt = 0; mt < MT; mt++)
                *(uint4*)a[mt] = *(const uint4*)&As[wm * MT + mt][kt][lane][0];
            unsigned b[NT][2];
#pragma unroll
            for (int nt = 0; nt < NT; nt++)
                *(uint2*)b[nt] = *(const uint2*)&Bs[wn * NT + nt][kt >> 1][lane][(kt & 1) * 2];
#pragma unroll
            for (int mt = 0; mt < MT; mt++)
#pragma unroll
                for (int nt = 0; nt < NT; nt++)
                    mma_tf32(acc[mt][nt], a[mt], b[nt]);
        }
        __syncthreads();
    }

#pragma unroll
    for (int mt = 0; mt < MT; mt++) {
#pragma unroll
        for (int nt = 0; nt < NT; nt++) {
            int col = bn + wn * (NT * 8) + nt * 8 + 2 * tig;
            int row0 = bm + wm * (MT * 16) + mt * 16 + g;
            float b0 = bias[col], b1 = bias[col + 1];
            float v0 = acc[mt][nt][0] + b0, v1 = acc[mt][nt][1] + b1;
            float v2 = acc[mt][nt][2] + b0, v3 = acc[mt][nt][3] + b1;
            if (RELU) {
                v0 = fmaxf(v0, 0.f); v1 = fmaxf(v1, 0.f);
                v2 = fmaxf(v2, 0.f); v3 = fmaxf(v3, 0.f);
            }
            int N_total = gridDim.y * BN;
            *(float2*)(C + (size_t)row0 * N_total + col)       = make_float2(v0, v1);
            *(float2*)(C + (size_t)(row0 + 8) * N_total + col) = make_float2(v2, v3);
        }
    }
}

// ---------------- scalar f32x2 GEMM (heads only, N=19) ----------------
template<int BM, int BN, int BK, int TM, int TN, bool RELU, bool NGUARD>
__global__ void __launch_bounds__((BM / TM) * (BN / TN))
gemm_kernel(const float* __restrict__ A, const float* __restrict__ W,
            const float* __restrict__ bias, float* __restrict__ C,
            int N, int K, int ldc) {
    constexpr int THREADS = (BM / TM) * (BN / TN);
    constexpr int BNQ = BN / TN;
    __shared__ __align__(16) float As[BK][BM + 4];
    __shared__ __align__(16) float Ws[BK][BN + 4];

    const int tid = threadIdx.x;
    const int bm = blockIdx.x * BM;
    const int bn = blockIdx.y * BN;
    const int tx = tid % BNQ;
    const int ty = tid / BNQ;

    ull acc2[TM / 2][TN];
#pragma unroll
    for (int i = 0; i < TM / 2; i++)
#pragma unroll
        for (int j = 0; j < TN; j++) acc2[i][j] = 0ull;

    for (int k0 = 0; k0 < K; k0 += BK) {
        constexpr int AV = BM * BK / 4;
#pragma unroll
        for (int i = 0; i < AV / THREADS; i++) {
            int idx = tid + i * THREADS;
            int row = idx / (BK / 4);
            int c4 = idx % (BK / 4);
            float4 v = *(const float4*)(A + (size_t)(bm + row) * K + k0 + c4 * 4);
            As[c4 * 4 + 0][row] = v.x;
            As[c4 * 4 + 1][row] = v.y;
            As[c4 * 4 + 2][row] = v.z;
            As[c4 * 4 + 3][row] = v.w;
        }
        constexpr int WV = BN * BK / 4;
#pragma unroll
        for (int i = 0; i < (WV + THREADS - 1) / THREADS; i++) {
            int idx = tid + i * THREADS;
            if ((WV % THREADS == 0) || idx < WV) {
                int row = idx / (BK / 4);
                int c4 = idx % (BK / 4);
                float4 v;
                if (!NGUARD || (bn + row) < N)
                    v = *(const float4*)(W + (size_t)(bn + row) * K + k0 + c4 * 4);
                else
                    v = make_float4(0.f, 0.f, 0.f, 0.f);
                Ws[c4 * 4 + 0][row] = v.x;
                Ws[c4 * 4 + 1][row] = v.y;
                Ws[c4 * 4 + 2][row] = v.z;
                Ws[c4 * 4 + 3][row] = v.w;
            }
        }
        __syncthreads();
#pragma unroll
        for (int kk = 0; kk < BK; kk++) {
            ull a2[TM / 2];
#pragma unroll
            for (int i2 = 0; i2 < TM / 2; i2++)
                a2[i2] = *(const ull*)&As[kk][ty * TM + 2 * i2];
            float br[TN];
#pragma unroll
            for (int j = 0; j < TN; j++) br[j] = Ws[kk][tx * TN + j];
            ull b2[TN];
#pragma unroll
            for (int j = 0; j < TN; j++) b2[j] = pack2(br[j], br[j]);
#pragma unroll
            for (int i2 = 0; i2 < TM / 2; i2++)
#pragma unroll
                for (int j = 0; j < TN; j++)
                    acc2[i2][j] = ffma2(a2[i2], b2[j], acc2[i2][j]);
        }
        __syncthreads();
    }
#pragma unroll
    for (int j = 0; j < TN; j++) {
        int n = bn + tx * TN + j;
        if (NGUARD && n >= N) continue;
        float bv = bias[n];
#pragma unroll
        for (int i2 = 0; i2 < TM / 2; i2++) {
            float v0, v1;
            unpack2(acc2[i2][j], v0, v1);
            v0 += bv; v1 += bv;
            if (RELU) { v0 = fmaxf(v0, 0.f); v1 = fmaxf(v1, 0.f); }
            C[(size_t)(bm + ty * TM + 2 * i2 + 0) * ldc + n] = v0;
            C[(size_t)(bm + ty * TM + 2 * i2 + 1) * ldc + n] = v1;
        }
    }
}

// ========== persistent tensor-core LSTM (v2: prefetch + balanced update) ====
// 128 CTAs x 512 threads (16 warps); CTA owns 8 batch rows for all 256 steps.
// Gate matrix rows [0,512) = [i | f | g | o]; tile t = rows [16t,16t+16).
// Warp w computes tiles {w, 16+w}:
//   w<8 : i[16w..] (sigmoid) + g[16w..] (tanh)
//   w>=8: f[16(w-8)..] (sigmoid) + o[16(w-8)..] (sigmoid)
// All gates go to smem gs[4][128j][8b]; then ALL 512 threads update 2 cells.
// xg + done for step+1 are prefetched during step's mma (hides DRAM latency).
#define LSTM2_SMEM ((SM_TILES * 2048 + 1024 + 4096) * 4)

__global__ void __launch_bounds__(512, 1)
lstm_tc_kernel(const float* __restrict__ xg, const float* __restrict__ done,
               const float* __restrict__ h0, const float* __restrict__ c0,
               float* __restrict__ hs, const float* __restrict__ frag) {
    extern __shared__ float sm[];
    float* smA = sm;                    // [SM_TILES][16][32][4]
    float* h_s = sm + SM_TILES * 2048;  // [128 j][8 b]  (tf32-rounded, masked)
    float* gs  = h_s + 1024;            // [4 gate][128 j][8 b]

    const int tid  = threadIdx.x;
    const int w    = tid >> 5;
    const int lane = tid & 31;
    const int gg   = lane >> 2;
    const int tg   = lane & 3;
    const int bb0  = blockIdx.x * 8;

    // cooperative load of resident A-fragment tiles
    {
        const uint4* src = (const uint4*)frag;
        uint4* dst = (uint4*)smA;
        for (int i = tid; i < SM_TILES * 512; i += 512) dst[i] = src[i];
    }
    // h_s init: h0 masked by done[0], tf32-rounded
    for (int i = tid; i < 1024; i += 512) {
        int j = i >> 3, b = i & 7;
        float m = 1.f - done[bb0 + b];
        h_s[i] = __uint_as_float(tf32_of(h0[(bb0 + b) * 128 + j] * m));
    }
    __syncthreads();

    // ---- mma-role constants ----
    const int jbase = 16 * (w & 7);       // j range of this warp's tiles
    const int n0 = w * 16 + gg;           // tile0 gate-row base (global 512-row idx)
    const int n1 = (16 + w) * 16 + gg;    // tile1
    const int bA = bb0 + 2 * tg;          // mma D-fragment batch cols
    const uint4* smT0   = (const uint4*)(smA + w * 2048);
    const uint4* smT1   = (const uint4*)(smA + (16 + w) * 2048);
    const uint4* fragT1 = (const uint4*)(frag + (16 + w) * 2048);
    const bool t1smem = (16 + w) < SM_TILES;

    // ---- update-role constants: thread owns cells (uj, ub) and (uj, ub+1) ----
    const int uj = tid >> 2;
    const int ub = 2 * (tid & 3);
    float cr0, cr1;
    {
        float m0 = 1.f - done[bb0 + ub];
        float m1 = 1.f - done[bb0 + ub + 1];
        cr0 = c0[(bb0 + ub) * 128 + uj] * m0;
        cr1 = c0[(bb0 + ub + 1) * 128 + uj] * m1;
    }

    // ---- xg prefetch for step 0 ----
    float x0[4], x1[4];
    {
        const float* xb  = xg + (size_t)bA * 512;
        const float* xb2 = xb + 512;
        x0[0] = xb[n0];     x0[1] = xb2[n0];
        x0[2] = xb[n0 + 8]; x0[3] = xb2[n0 + 8];
        x1[0] = xb[n1];     x1[1] = xb2[n1];
        x1[2] = xb[n1 + 8]; x1[3] = xb2[n1 + 8];
    }

    for (int step = 0; step < TT; ++step) {
        // prefetch xg + done masks for step+1 (consumed next iter / end of this one)
        float nx0[4], nx1[4];
        float md0 = 0.f, md1 = 0.f;   // (end-of-sequence: h,c unused after)
        if (step + 1 < TT) {
            const float* xb  = xg + ((size_t)(step + 1) * BB + bA) * 512;
            const float* xb2 = xb + 512;
            nx0[0] = xb[n0];     nx0[1] = xb2[n0];
            nx0[2] = xb[n0 + 8]; nx0[3] = xb2[n0 + 8];
            nx1[0] = xb[n1];     nx1[1] = xb2[n1];
            nx1[2] = xb[n1 + 8]; nx1[3] = xb2[n1 + 8];
            md0 = 1.f - done[(size_t)(step + 1) * BB + bb0 + ub];
            md1 = 1.f - done[(size_t)(step + 1) * BB + bb0 + ub + 1];
        }

        // ---- G = Whh-tiles @ h  (two independent mma chains) ----
        float acc0[4] = {0.f, 0.f, 0.f, 0.f};
        float acc1[4] = {0.f, 0.f, 0.f, 0.f};

        if (t1smem) {
#pragma unroll
            for (int ks = 0; ks < 16; ks++) {
                unsigned b_[2];
                b_[0] = __float_as_uint(h_s[(ks * 8 + tg) * 8 + gg]);
                b_[1] = __float_as_uint(h_s[(ks * 8 + 4 + tg) * 8 + gg]);
                uint4 a0 = smT0[ks * 32 + lane];
                uint4 a1 = smT1[ks * 32 + lane];
                mma_tf32(acc0, (const unsigned*)&a0, b_);
                mma_tf32(acc1, (const unsigned*)&a1, b_);
            }
        } else {
            uint4 pf[16];
#pragma unroll
            for (int ks = 0; ks < 16; ks++) pf[ks] = fragT1[ks * 32 + lane];
#pragma unroll
            for (int ks = 0; ks < 16; ks++) {
                unsigned b_[2];
                b_[0] = __float_as_uint(h_s[(ks * 8 + tg) * 8 + gg]);
                b_[1] = __float_as_uint(h_s[(ks * 8 + 4 + tg) * 8 + gg]);
                uint4 a0 = smT0[ks * 32 + lane];
                mma_tf32(acc0, (const unsigned*)&a0, b_);
                mma_tf32(acc1, (const unsigned*)&pf[ks], b_);
            }
        }

        // ---- activations + scatter all 4 gates to smem ----
        // acc0: i (w<8) or f (w>=8)  -> sigmoid
        // acc1: g (w<8, tanh) or o (w>=8, sigmoid)
        const int g0off = (w < 8) ? 0 : 1024;         // i : f
        const int g1off = (w < 8) ? 2048 : 3072;      // g : o
#pragma unroll
        for (int r = 0; r < 4; r++) {
            float v0 = acc0[r] + x0[r];
            float v1 = acc1[r] + x1[r];
            float a0 = sigmoid_f(v0);
            float a1 = (w < 8) ? tanh_f(v1) : sigmoid_f(v1);
            int j = jbase + gg + ((r & 2) ? 8 : 0);
            int b = 2 * tg + (r & 1);
            gs[g0off + j * 8 + b] = a0;
            gs[g1off + j * 8 + b] = a1;
        }
        __syncthreads();

        // ---- balanced cell update: every thread owns 2 cells ----
        {
            int base = uj * 8 + ub;
            float2 iv = *(const float2*)&gs[base];
            float2 fv = *(const float2*)&gs[1024 + base];
            float2 gv = *(const float2*)&gs[2048 + base];
            float2 ov = *(const float2*)&gs[3072 + base];

            cr0 = fv.x * cr0 + iv.x * gv.x;
            cr1 = fv.y * cr1 + iv.y * gv.y;
            float hv0 = ov.x * tanh_f(cr0);
            float hv1 = ov.y * tanh_f(cr1);

            hs[((size_t)step * BB + bb0 + ub) * 128 + uj]     = hv0;
            hs[((size_t)step * BB + bb0 + ub + 1) * 128 + uj] = hv1;

            cr0 *= md0;
            cr1 *= md1;
            *(float2*)&h_s[base] = make_float2(
                __uint_as_float(tf32_of(hv0 * md0)),
                __uint_as_float(tf32_of(hv1 * md1)));
        }
        __syncthreads();

#pragma unroll
        for (int r = 0; r < 4; r++) { x0[r] = nx0[r]; x1[r] = nx1[r]; }
    }
}

// ---------------- launch ----------------
extern "C" void kernel_launch(void* const* d_in, const int* in_sizes, int n_in,
                              void* d_out, int out_size) {
    const float* x    = (const float*)d_in[0];
    const float* done = (const float*)d_in[1];
    const float* h0   = (const float*)d_in[2];
    const float* c0   = (const float*)d_in[3];
    const float* W1   = (const float*)d_in[4];
    const float* b1   = (const float*)d_in[5];
    const float* W2   = (const float*)d_in[6];
    const float* b2   = (const float*)d_in[7];
    const float* W3   = (const float*)d_in[8];
    const float* b3   = (const float*)d_in[9];
    const float* Wih  = (const float*)d_in[10];
    const float* Whh  = (const float*)d_in[11];
    const float* bih  = (const float*)d_in[12];
    const float* bhh  = (const float*)d_in[13];
    const float* Wa   = (const float*)d_in[14];
    const float* ba   = (const float*)d_in[15];
    const float* Wc   = (const float*)d_in[16];
    const float* bc   = (const float*)d_in[17];
    float* out = (float*)d_out;

    float *h1, *h2, *h3, *xgp, *hsp, *fragp, *bg, *whd, *bhd;
    cudaGetSymbolAddress((void**)&h1,    g_h1);
    cudaGetSymbolAddress((void**)&h2,    g_h2);
    cudaGetSymbolAddress((void**)&h3,    g_h3);
    cudaGetSymbolAddress((void**)&xgp,   g_xg);
    cudaGetSymbolAddress((void**)&hsp,   g_hs);
    cudaGetSymbolAddress((void**)&fragp, g_WhhFrag);
    cudaGetSymbolAddress((void**)&bg,    g_bg);
    cudaGetSymbolAddress((void**)&whd,   g_Whead);
    cudaGetSymbolAddress((void**)&bhd,   g_bhead);

    static int smem_set = 0;
    if (!smem_set) {
        cudaFuncSetAttribute(lstm_tc_kernel,
                             cudaFuncAttributeMaxDynamicSharedMemorySize,
                             LSTM2_SMEM);
        smem_set = 1;
    }

    prepack_kernel<<<128, 256>>>(Whh, bih, bhh, Wa, ba, Wc, bc);

    // MLP encoder (tf32 tensor cores)
    tf32_gemm<128, 4, 2, true><<<dim3(TB / 128, 1), 256>>>(x,  W1, b1, h1, 128);
    tf32_gemm< 32, 8, 1, true><<<dim3(TB / 128, 1), 256>>>(h1, W2, b2, h2, 128);
    tf32_gemm<128, 4, 2, true><<<dim3(TB / 128, 1), 256>>>(h2, W3, b3, h3, 32);

    // xg = h3 @ Wih^T + (bih+bhh)
    tf32_gemm<256, 2, 4, false><<<dim3(TB / 128, 2), 256>>>(h3, Wih, bg, xgp, 128);

    // Sequential LSTM (tensor-core recurrence)
    lstm_tc_kernel<<<128, 512, LSTM2_SMEM>>>(xgp, done, h0, c0, hsp, fragp);

    // Heads (fp32 scalar, N=19)
    gemm_kernel<128, 32, 32, 8, 2, false, true>
        <<<dim3(TB / 128, 1), 256>>>(hsp, whd, bhd, out, NOUT, 128, NOUT);
}

// round 11
// speedup vs baseline: 1.0234x; 1.0234x over previous
#include <cuda_runtime.h>
#include <math.h>

// Problem dims
#define TB   262144   // T*B = 256*1024
#define TT   256
#define BB   1024
#define NOUT 19
#define SM_TILES 26   // A-fragment m-tiles resident in smem (of 32)

// ---------------- scratch (static device memory; no allocs) ----------------
__device__ float g_h1[TB * 128];
__device__ float g_h2[TB * 32];
__device__ float g_h3[TB * 128];
__device__ float g_xg[TB * 512];
__device__ float g_hs[TB * 128];
__device__ float g_WhhFrag[32 * 16 * 32 * 4];  // [mtile][kstep][lane][reg], tf32
__device__ float g_bg[512];
__device__ float g_Whead[NOUT * 128];
__device__ float g_bhead[NOUT];

// ---------------- packed f32x2 helpers ----------------
typedef unsigned long long ull;
__device__ __forceinline__ ull pack2(float lo, float hi) {
    ull r; asm("mov.b64 %0, {%1, %2};" : "=l"(r) : "f"(lo), "f"(hi)); return r;
}
__device__ __forceinline__ void unpack2(ull p, float& lo, float& hi) {
    asm("mov.b64 {%0, %1}, %2;" : "=f"(lo), "=f"(hi) : "l"(p));
}
__device__ __forceinline__ ull ffma2(ull a, ull b, ull c) {
    ull d; asm("fma.rn.f32x2 %0, %1, %2, %3;" : "=l"(d) : "l"(a), "l"(b), "l"(c));
    return d;
}

// ---------------- tf32 helpers ----------------
__device__ __forceinline__ unsigned tf32_of(float f) {
    unsigned r; asm("cvt.rna.tf32.f32 %0, %1;" : "=r"(r) : "f"(f)); return r;
}
__device__ __forceinline__ void mma_tf32(float* d, const unsigned* a, const unsigned* b) {
    asm volatile(
        "mma.sync.aligned.m16n8k8.row.col.f32.tf32.tf32.f32 "
        "{%0,%1,%2,%3}, {%4,%5,%6,%7}, {%8,%9}, {%0,%1,%2,%3};"
        : "+f"(d[0]), "+f"(d[1]), "+f"(d[2]), "+f"(d[3])
        : "r"(a[0]), "r"(a[1]), "r"(a[2]), "r"(a[3]), "r"(b[0]), "r"(b[1]));
}

// ---------------- fast activations ----------------
__device__ __forceinline__ float sigmoid_f(float x) {
    return __fdividef(1.f, 1.f + __expf(-x));
}
__device__ __forceinline__ float tanh_f(float x) {
    float e = __expf(-2.f * fabsf(x));
    float r = __fdividef(1.f - e, 1.f + e);
    return copysignf(r, x);
}

// ---------------- prepack ----------------
// g_WhhFrag[mt][ks][lane][r]: exact mma.m16n8k8 A-fragment order (row-major A):
//   g = lane>>2, t = lane&3
//   r0=(g,t)  r1=(g+8,t)  r2=(g,t+4)  r3=(g+8,t+4)   rows = gates, cols = k
__global__ void prepack_kernel(const float* __restrict__ Whh,
                               const float* __restrict__ bih,
                               const float* __restrict__ bhh,
                               const float* __restrict__ Wa,
                               const float* __restrict__ ba,
                               const float* __restrict__ Wc,
                               const float* __restrict__ bc) {
    int t = blockIdx.x * blockDim.x + threadIdx.x;
    int stride = gridDim.x * blockDim.x;
    for (int i = t; i < 32 * 16 * 32 * 4; i += stride) {
        int r    = i & 3;
        int lane = (i >> 2) & 31;
        int ks   = (i >> 7) & 15;
        int mt   = i >> 11;
        int gg = lane >> 2, tg = lane & 3;
        int row = mt * 16 + gg + ((r & 1) ? 8 : 0);
        int col = ks * 8 + tg + ((r & 2) ? 4 : 0);
        g_WhhFrag[i] = __uint_as_float(tf32_of(Whh[row * 128 + col]));
    }
    if (t < 512) g_bg[t] = bih[t] + bhh[t];
    for (int i = t; i < NOUT * 128; i += stride) {
        int n = i / 128, k = i % 128;
        g_Whead[i] = (n < 18) ? Wa[n * 128 + k] : Wc[k];
    }
    if (t < NOUT) g_bhead[t] = (t < 18) ? ba[t] : bc[0];
}

// ================= TF32 tensor-core GEMM (feedforward) =================
template<int BN, int WARPS_M, int WARPS_N, bool RELU>
__global__ void __launch_bounds__(32 * WARPS_M * WARPS_N, 2)
tf32_gemm(const float* __restrict__ A, const float* __restrict__ W,
          const float* __restrict__ bias, float* __restrict__ C, int K) {
    constexpr int BM = 128;
    constexpr int BK = 32;
    constexpr int THREADS = 32 * WARPS_M * WARPS_N;
    constexpr int MT = (BM / WARPS_M) / 16;
    constexpr int NT = (BN / WARPS_N) / 8;

    __shared__ unsigned As[BM / 16][BK / 8][32][4];
    __shared__ unsigned Bs[BN / 8][BK / 16][32][4];

    const int tid  = threadIdx.x;
    const int lane = tid & 31;
    const int w    = tid >> 5;
    const int wm   = w / WARPS_N;
    const int wn   = w % WARPS_N;
    const int bm   = blockIdx.x * BM;
    const int bn   = blockIdx.y * BN;
    const int g    = lane >> 2;
    const int tig  = lane & 3;

    float acc[MT][NT][4];
#pragma unroll
    for (int i = 0; i < MT; i++)
#pragma unroll
        for (int j = 0; j < NT; j++)
#pragma unroll
            for (int r = 0; r < 4; r++) acc[i][j][r] = 0.f;

    for (int k0 = 0; k0 < K; k0 += BK) {
        constexpr int AV4 = BM * BK / 4;
#pragma unroll
        for (int it = 0; it < AV4 / THREADS; it++) {
            int idx = tid + it * THREADS;
            int row = idx >> 3;
            int c4  = idx & 7;
            float4 v = *(const float4*)(A + (size_t)(bm + row) * K + k0 + c4 * 4);
            int mt = row >> 4, r = row & 15;
            float vv[4] = {v.x, v.y, v.z, v.w};
#pragma unroll
            for (int j = 0; j < 4; j++) {
                int col = c4 * 4 + j;
                int kt = col >> 3, c = col & 7;
                As[mt][kt][(r & 7) * 4 + (c & 3)][(r >> 3) + 2 * (c >> 2)] = tf32_of(vv[j]);
            }
        }
        constexpr int BV4 = BN * BK / 4;
#pragma unroll
        for (int it = 0; it < (BV4 + THREADS - 1) / THREADS; it++) {
            int idx = tid + it * THREADS;
            if ((BV4 % THREADS == 0) || idx < BV4) {
                int n  = idx >> 3;
                int c4 = idx & 7;
                float4 v = *(const float4*)(W + (size_t)(bn + n) * K + k0 + c4 * 4);
                int nt = n >> 3, gg = n & 7;
                float vv[4] = {v.x, v.y, v.z, v.w};
#pragma unroll
                for (int j = 0; j < 4; j++) {
                    int k = c4 * 4 + j;
                    int kblk = k >> 4, kk = k & 15;
                    Bs[nt][kblk][gg * 4 + (kk & 3)][((kk >> 3) << 1) + ((kk & 7) >> 2)] = tf32_of(vv[j]);
                }
            }
        }
        __syncthreads();

#pragma unroll
        for (int kt = 0; kt < 4; kt++) {
            unsigned a[MT][4];
#pragma unroll
            for (int mt = 0; mt < MT; mt++)
                *(uint4*)a[mt] = *(const uint4*)&As[wm * MT + mt][kt][lane][0];
            unsigned b[NT][2];
#pragma unroll
            for (int nt = 0; nt < NT; nt++)
                *(uint2*)b[nt] = *(const uint2*)&Bs[wn * NT + nt][kt >> 1][lane][(kt & 1) * 2];
#pragma unroll
            for (int mt = 0; mt < MT; mt++)
#pragma unroll
                for (int nt = 0; nt < NT; nt++)
                    mma_tf32(acc[mt][nt], a[mt], b[nt]);
        }
        __syncthreads();
    }

#pragma unroll
    for (int mt = 0; mt < MT; mt++) {
#pragma unroll
        for (int nt = 0; nt < NT; nt++) {
            int col = bn + wn * (NT * 8) + nt * 8 + 2 * tig;
            int row0 = bm + wm * (MT * 16) + mt * 16 + g;
            float b0 = bias[col], b1 = bias[col + 1];
            float v0 = acc[mt][nt][0] + b0, v1 = acc[mt][nt][1] + b1;
            float v2 = acc[mt][nt][2] + b0, v3 = acc[mt][nt][3] + b1;
            if (RELU) {
                v0 = fmaxf(v0, 0.f); v1 = fmaxf(v1, 0.f);
                v2 = fmaxf(v2, 0.f); v3 = fmaxf(v3, 0.f);
            }
            int N_total = gridDim.y * BN;
            *(float2*)(C + (size_t)row0 * N_total + col)       = make_float2(v0, v1);
            *(float2*)(C + (size_t)(row0 + 8) * N_total + col) = make_float2(v2, v3);
        }
    }
}

// ---------------- scalar f32x2 GEMM (heads only, N=19) ----------------
template<int BM, int BN, int BK, int TM, int TN, bool RELU, bool NGUARD>
__global__ void __launch_bounds__((BM / TM) * (BN / TN))
gemm_kernel(const float* __restrict__ A, const float* __restrict__ W,
            const float* __restrict__ bias, float* __restrict__ C,
            int N, int K, int ldc) {
    constexpr int THREADS = (BM / TM) * (BN / TN);
    constexpr int BNQ = BN / TN;
    __shared__ __align__(16) float As[BK][BM + 4];
    __shared__ __align__(16) float Ws[BK][BN + 4];

    const int tid = threadIdx.x;
    const int bm = blockIdx.x * BM;
    const int bn = blockIdx.y * BN;
    const int tx = tid % BNQ;
    const int ty = tid / BNQ;

    ull acc2[TM / 2][TN];
#pragma unroll
    for (int i = 0; i < TM / 2; i++)
#pragma unroll
        for (int j = 0; j < TN; j++) acc2[i][j] = 0ull;

    for (int k0 = 0; k0 < K; k0 += BK) {
        constexpr int AV = BM * BK / 4;
#pragma unroll
        for (int i = 0; i < AV / THREADS; i++) {
            int idx = tid + i * THREADS;
            int row = idx / (BK / 4);
            int c4 = idx % (BK / 4);
            float4 v = *(const float4*)(A + (size_t)(bm + row) * K + k0 + c4 * 4);
            As[c4 * 4 + 0][row] = v.x;
            As[c4 * 4 + 1][row] = v.y;
            As[c4 * 4 + 2][row] = v.z;
            As[c4 * 4 + 3][row] = v.w;
        }
        constexpr int WV = BN * BK / 4;
#pragma unroll
        for (int i = 0; i < (WV + THREADS - 1) / THREADS; i++) {
            int idx = tid + i * THREADS;
            if ((WV % THREADS == 0) || idx < WV) {
                int row = idx / (BK / 4);
                int c4 = idx % (BK / 4);
                float4 v;
                if (!NGUARD || (bn + row) < N)
                    v = *(const float4*)(W + (size_t)(bn + row) * K + k0 + c4 * 4);
                else
                    v = make_float4(0.f, 0.f, 0.f, 0.f);
                Ws[c4 * 4 + 0][row] = v.x;
                Ws[c4 * 4 + 1][row] = v.y;
                Ws[c4 * 4 + 2][row] = v.z;
                Ws[c4 * 4 + 3][row] = v.w;
            }
        }
        __syncthreads();
#pragma unroll
        for (int kk = 0; kk < BK; kk++) {
            ull a2[TM / 2];
#pragma unroll
            for (int i2 = 0; i2 < TM / 2; i2++)
                a2[i2] = *(const ull*)&As[kk][ty * TM + 2 * i2];
            float br[TN];
#pragma unroll
            for (int j = 0; j < TN; j++) br[j] = Ws[kk][tx * TN + j];
            ull b2[TN];
#pragma unroll
            for (int j = 0; j < TN; j++) b2[j] = pack2(br[j], br[j]);
#pragma unroll
            for (int i2 = 0; i2 < TM / 2; i2++)
#pragma unroll
                for (int j = 0; j < TN; j++)
                    acc2[i2][j] = ffma2(a2[i2], b2[j], acc2[i2][j]);
        }
        __syncthreads();
    }
#pragma unroll
    for (int j = 0; j < TN; j++) {
        int n = bn + tx * TN + j;
        if (NGUARD && n >= N) continue;
        float bv = bias[n];
#pragma unroll
        for (int i2 = 0; i2 < TM / 2; i2++) {
            float v0, v1;
            unpack2(acc2[i2][j], v0, v1);
            v0 += bv; v1 += bv;
            if (RELU) { v0 = fmaxf(v0, 0.f); v1 = fmaxf(v1, 0.f); }
            C[(size_t)(bm + ty * TM + 2 * i2 + 0) * ldc + n] = v0;
            C[(size_t)(bm + ty * TM + 2 * i2 + 1) * ldc + n] = v1;
        }
    }
}

// ========== persistent tensor-core LSTM (R9 structure + prefetch + split) ===
// 128 CTAs x 512 threads (16 warps); CTA owns 8 batch rows for all 256 steps.
// G[512 gates, 8 batch] per step via mma.m16n8k8 (gates=M, batch=N, k=128).
// Warp w computes m-tiles {w, 16+w}:
//   w<8 : i-gates [16w,16w+16) + g-gates (same j)   -> keeps c in registers
//   w>=8: f-gates + o-gates (same j)                -> exchange via 8KB smem
// A-fragments: tiles 0..SM_TILES-1 in smem, rest reg-prefetched from L2.
// xg for step+1 is prefetched during step's mma (hides DRAM latency).
// Each mma chain is split into two 8-deep halves (RAW latency halved).
#define LSTM2_SMEM ((SM_TILES * 2048 + 1024 + 2048) * 4)

__global__ void __launch_bounds__(512, 1)
lstm_tc_kernel(const float* __restrict__ xg, const float* __restrict__ done,
               const float* __restrict__ h0, const float* __restrict__ c0,
               float* __restrict__ hs, const float* __restrict__ frag) {
    extern __shared__ float sm[];
    float* smA = sm;                    // [SM_TILES][16][32][4]
    float* h_s = sm + SM_TILES * 2048;  // [128 j][8 b]  (tf32-rounded, masked)
    float* ex  = h_s + 1024;            // [2][128 j][8 b]  (f, o exchange)

    const int tid  = threadIdx.x;
    const int w    = tid >> 5;
    const int lane = tid & 31;
    const int gg   = lane >> 2;
    const int tg   = lane & 3;
    const int bb0  = blockIdx.x * 8;

    // cooperative load of resident A-fragment tiles
    {
        const uint4* src = (const uint4*)frag;
        uint4* dst = (uint4*)smA;
        for (int i = tid; i < SM_TILES * 512; i += 512) dst[i] = src[i];
    }
    // h_s init: h0 masked by done[0], tf32-rounded
    for (int i = tid; i < 1024; i += 512) {
        int j = i >> 3, b = i & 7;
        float m = 1.f - done[bb0 + b];
        h_s[i] = __uint_as_float(tf32_of(h0[(bb0 + b) * 128 + j] * m));
    }
    __syncthreads();

    const int j0 = 16 * w + gg;         // cell row base (valid w<8)
    const int bA = bb0 + 2 * tg;
    const int bB = bA + 1;

    float c[4] = {0.f, 0.f, 0.f, 0.f};
    if (w < 8) {
        float mA = 1.f - done[bA], mB = 1.f - done[bB];
        c[0] = c0[bA * 128 + j0] * mA;
        c[1] = c0[bB * 128 + j0] * mB;
        c[2] = c0[bA * 128 + j0 + 8] * mA;
        c[3] = c0[bB * 128 + j0 + 8] * mB;
    }

    const int n0 = w * 16 + gg;           // tile0 gate index base
    const int n1 = (16 + w) * 16 + gg;    // tile1
    const uint4* smT0   = (const uint4*)(smA + w * 2048);
    const uint4* smT1   = (const uint4*)(smA + (16 + w) * 2048);
    const uint4* fragT1 = (const uint4*)(frag + (16 + w) * 2048);
    const bool t1smem = (16 + w) < SM_TILES;

    // ---- xg prefetch for step 0 ----
    float x0[4], x1[4];
    {
        const float* xb  = xg + (size_t)bA * 512;
        const float* xb2 = xb + 512;
        x0[0] = xb[n0];     x0[1] = xb2[n0];
        x0[2] = xb[n0 + 8]; x0[3] = xb2[n0 + 8];
        x1[0] = xb[n1];     x1[1] = xb2[n1];
        x1[2] = xb[n1 + 8]; x1[3] = xb2[n1 + 8];
    }

    for (int step = 0; step < TT; ++step) {
        // prefetch xg + next-step done masks (in flight during the mma chain)
        float nx0[4] = {0.f, 0.f, 0.f, 0.f};
        float nx1[4] = {0.f, 0.f, 0.f, 0.f};
        float mA2 = 1.f, mB2 = 1.f;
        if (step + 1 < TT) {
            const float* xb  = xg + ((size_t)(step + 1) * BB + bA) * 512;
            const float* xb2 = xb + 512;
            nx0[0] = xb[n0];     nx0[1] = xb2[n0];
            nx0[2] = xb[n0 + 8]; nx0[3] = xb2[n0 + 8];
            nx1[0] = xb[n1];     nx1[1] = xb2[n1];
            nx1[2] = xb[n1 + 8]; nx1[3] = xb2[n1 + 8];
            if (w < 8) {
                mA2 = 1.f - done[(size_t)(step + 1) * BB + bA];
                mB2 = 1.f - done[(size_t)(step + 1) * BB + bB];
            }
        }

        // ---- G = Whh-tiles @ h : two tiles x two 8-deep half-chains ----
        float acc0[4] = {0.f, 0.f, 0.f, 0.f};
        float acc0b[4] = {0.f, 0.f, 0.f, 0.f};
        float acc1[4] = {0.f, 0.f, 0.f, 0.f};
        float acc1b[4] = {0.f, 0.f, 0.f, 0.f};

        if (t1smem) {
#pragma unroll
            for (int ks = 0; ks < 8; ks++) {
                unsigned bl[2], bh[2];
                bl[0] = __float_as_uint(h_s[(ks * 8 + tg) * 8 + gg]);
                bl[1] = __float_as_uint(h_s[(ks * 8 + 4 + tg) * 8 + gg]);
                bh[0] = __float_as_uint(h_s[((ks + 8) * 8 + tg) * 8 + gg]);
                bh[1] = __float_as_uint(h_s[((ks + 8) * 8 + 4 + tg) * 8 + gg]);
                uint4 a0l = smT0[ks * 32 + lane];
                uint4 a0h = smT0[(ks + 8) * 32 + lane];
                uint4 a1l = smT1[ks * 32 + lane];
                uint4 a1h = smT1[(ks + 8) * 32 + lane];
                mma_tf32(acc0,  (const unsigned*)&a0l, bl);
                mma_tf32(acc0b, (const unsigned*)&a0h, bh);
                mma_tf32(acc1,  (const unsigned*)&a1l, bl);
                mma_tf32(acc1b, (const unsigned*)&a1h, bh);
            }
        } else {
            // batch-issue L2 prefetch of tile1 fragments (MLP=16)
            uint4 pf[16];
#pragma unroll
            for (int ks = 0; ks < 16; ks++) pf[ks] = fragT1[ks * 32 + lane];
#pragma unroll
            for (int ks = 0; ks < 8; ks++) {
                unsigned bl[2], bh[2];
                bl[0] = __float_as_uint(h_s[(ks * 8 + tg) * 8 + gg]);
                bl[1] = __float_as_uint(h_s[(ks * 8 + 4 + tg) * 8 + gg]);
                bh[0] = __float_as_uint(h_s[((ks + 8) * 8 + tg) * 8 + gg]);
                bh[1] = __float_as_uint(h_s[((ks + 8) * 8 + 4 + tg) * 8 + gg]);
                uint4 a0l = smT0[ks * 32 + lane];
                uint4 a0h = smT0[(ks + 8) * 32 + lane];
                mma_tf32(acc0,  (const unsigned*)&a0l, bl);
                mma_tf32(acc0b, (const unsigned*)&a0h, bh);
                mma_tf32(acc1,  (const unsigned*)&pf[ks], bl);
                mma_tf32(acc1b, (const unsigned*)&pf[ks + 8], bh);
            }
        }
#pragma unroll
        for (int r = 0; r < 4; r++) {
            acc0[r] += acc0b[r];
            acc1[r] += acc1b[r];
        }

        float ig[4], gt[4];
        if (w >= 8) {
            // f = sigmoid(tile w), o = sigmoid(tile 16+w) -> smem exchange
            int jj = (w - 8) * 16 + gg;
#pragma unroll
            for (int r = 0; r < 4; r++) {
                float fv = sigmoid_f(acc0[r] + x0[r]);
                float ov = sigmoid_f(acc1[r] + x1[r]);
                int j = jj + ((r & 2) ? 8 : 0);
                int b = 2 * tg + (r & 1);
                ex[j * 8 + b]        = fv;
                ex[1024 + j * 8 + b] = ov;
            }
        } else {
#pragma unroll
            for (int r = 0; r < 4; r++) {
                ig[r] = sigmoid_f(acc0[r] + x0[r]);   // i-gate
                gt[r] = tanh_f(acc1[r] + x1[r]);      // g-gate
            }
        }
        __syncthreads();

        if (w < 8) {
#pragma unroll
            for (int r = 0; r < 4; r++) {
                int j = j0 + ((r & 2) ? 8 : 0);
                int b = 2 * tg + (r & 1);
                float fv = ex[j * 8 + b];
                float ov = ex[1024 + j * 8 + b];
                c[r] = fv * c[r] + ig[r] * gt[r];
                float hv = ov * tanh_f(c[r]);
                hs[((size_t)step * BB + bb0 + b) * 128 + j] = hv;
                float m = (r & 1) ? mB2 : mA2;
                c[r] *= m;
                h_s[j * 8 + b] = __uint_as_float(tf32_of(hv * m));
            }
        }
        __syncthreads();

#pragma unroll
        for (int r = 0; r < 4; r++) { x0[r] = nx0[r]; x1[r] = nx1[r]; }
    }
}

// ---------------- launch ----------------
extern "C" void kernel_launch(void* const* d_in, const int* in_sizes, int n_in,
                              void* d_out, int out_size) {
    const float* x    = (const float*)d_in[0];
    const float* done = (const float*)d_in[1];
    const float* h0   = (const float*)d_in[2];
    const float* c0   = (const float*)d_in[3];
    const float* W1   = (const float*)d_in[4];
    const float* b1   = (const float*)d_in[5];
    const float* W2   = (const float*)d_in[6];
    const float* b2   = (const float*)d_in[7];
    const float* W3   = (const float*)d_in[8];
    const float* b3   = (const float*)d_in[9];
    const float* Wih  = (const float*)d_in[10];
    const float* Whh  = (const float*)d_in[11];
    const float* bih  = (const float*)d_in[12];
    const float* bhh  = (const float*)d_in[13];
    const float* Wa   = (const float*)d_in[14];
    const float* ba   = (const float*)d_in[15];
    const float* Wc   = (const float*)d_in[16];
    const float* bc   = (const float*)d_in[17];
    float* out = (float*)d_out;

    float *h1, *h2, *h3, *xgp, *hsp, *fragp, *bg, *whd, *bhd;
    cudaGetSymbolAddress((void**)&h1,    g_h1);
    cudaGetSymbolAddress((void**)&h2,    g_h2);
    cudaGetSymbolAddress((void**)&h3,    g_h3);
    cudaGetSymbolAddress((void**)&xgp,   g_xg);
    cudaGetSymbolAddress((void**)&hsp,   g_hs);
    cudaGetSymbolAddress((void**)&fragp, g_WhhFrag);
    cudaGetSymbolAddress((void**)&bg,    g_bg);
    cudaGetSymbolAddress((void**)&whd,   g_Whead);
    cudaGetSymbolAddress((void**)&bhd,   g_bhead);

    static int smem_set = 0;
    if (!smem_set) {
        cudaFuncSetAttribute(lstm_tc_kernel,
                             cudaFuncAttributeMaxDynamicSharedMemorySize,
                             LSTM2_SMEM);
        smem_set = 1;
    }

    prepack_kernel<<<128, 256>>>(Whh, bih, bhh, Wa, ba, Wc, bc);

    // MLP encoder (tf32 tensor cores)
    tf32_gemm<128, 4, 2, true><<<dim3(TB / 128, 1), 256>>>(x,  W1, b1, h1, 128);
    tf32_gemm< 32, 8, 1, true><<<dim3(TB / 128, 1), 256>>>(h1, W2, b2, h2, 128);
    tf32_gemm<128, 4, 2, true><<<dim3(TB / 128, 1), 256>>>(h2, W3, b3, h3, 32);

    // xg = h3 @ Wih^T + (bih+bhh)
    tf32_gemm<256, 2, 4, false><<<dim3(TB / 128, 2), 256>>>(h3, Wih, bg, xgp, 128);

    // Sequential LSTM (tensor-core recurrence)
    lstm_tc_kernel<<<128, 512, LSTM2_SMEM>>>(xgp, done, h0, c0, hsp, fragp);

    // Heads (fp32 scalar, N=19)
    gemm_kernel<128, 32, 32, 8, 2, false, true>
        <<<dim3(TB / 128, 1), 256>>>(hsp, whd, bhd, out, NOUT, 128, NOUT);
}